// round 3
// baseline (speedup 1.0000x reference)
#include <cuda_runtime.h>
#include <cuda_fp16.h>
#include <cstdint>

// Problem dims (fixed): X:(B,N), boundaries:(N,K+1), weight:(N,K,E), bias:(N,E)
#define BDIM 4096
#define NDIM 64
#define KDIM 128
#define EDIM 512
#define EPS_F 1e-8f

// Prefix table T[n][k][e] (fp16): T[n][k][e] = bias[n][e] + sum_{j<k} w[n][j][e]
// out[b][n][e] = relu( lerp(T[n][bidx], T[n][bidx+1], frac) )
__device__ __half g_T16[(size_t)NDIM * (KDIM + 1) * EDIM];
// Per-(b,n) precomputed (frac, bidx) — indexed b*N+n to match X layout.
__device__ float2 g_SF[(size_t)BDIM * NDIM];

#define PREFIX_BLOCKS ((NDIM * 4 * EDIM) / 256)        // 512
#define SEARCH_BLOCKS ((BDIM * NDIM) / 256)            // 1024

// ---------------------------------------------------------------------------
// Setup kernel (fused): blocks [0,512) build the fp16 prefix table (4 k-chunks
// of 32 per (n,e) for parallelism); blocks [512,1536) do one binary search per
// thread over all (b,n) pairs, writing (frac, bidx) to g_SF.
// ---------------------------------------------------------------------------
__global__ void setup_kernel(const float* __restrict__ X,
                             const float* __restrict__ bnd,
                             const float* __restrict__ weight,
                             const float* __restrict__ bias) {
    if (blockIdx.x < PREFIX_BLOCKS) {
        int t = blockIdx.x * blockDim.x + threadIdx.x;   // 0 .. N*4*E-1
        int e   = t % EDIM;
        int tmp = t / EDIM;          // n*4 + c
        int c   = tmp & 3;
        int n   = tmp >> 2;

        const float* wp = weight + (size_t)n * KDIM * EDIM + e;
        __half*      Tp = g_T16  + (size_t)n * (KDIM + 1) * EDIM + e;

        float acc = bias[n * EDIM + e];
        const int k0 = c * 32;

#pragma unroll 8
        for (int k = 0; k < k0; k++)               // redundant base sum
            acc += wp[(size_t)k * EDIM];

#pragma unroll
        for (int k = k0; k < k0 + 32; k++) {       // scan this chunk
            Tp[(size_t)k * EDIM] = __float2half_rn(acc);
            acc += wp[(size_t)k * EDIM];
        }
        if (c == 3)
            Tp[(size_t)KDIM * EDIM] = __float2half_rn(acc);
    } else {
        int i = (blockIdx.x - PREFIX_BLOCKS) * blockDim.x + threadIdx.x; // b*N+n
        int n = i & (NDIM - 1);
        const float x = X[i];
        const float* bn = bnd + (size_t)n * (KDIM + 1);

        // lower_bound over inner boundaries bn[1..K-1]: lo in [0, K-1]
        int lo = 0, len = KDIM - 1;
        while (len > 0) {
            int half = len >> 1;
            bool pred = __ldg(&bn[1 + lo + half]) < x;
            lo  += pred ? (half + 1) : 0;
            len  = pred ? (len - half - 1) : half;
        }
        const float s  = __ldg(&bn[lo]);
        const float eb = __ldg(&bn[lo + 1]);
        const float frac = (x - s) / (eb - s + EPS_F);
        g_SF[i] = make_float2(frac, __int_as_float(lo));
    }
}

// ---------------------------------------------------------------------------
// Gather kernel: one warp per (b,n). Reads precomputed (frac,lo), then
// immediately issues all 4 table LDG.128 (no dependent search chain), lerps
// in fp32, streams out 8 float4 via __stcs (write-once data, don't pollute L2).
// ---------------------------------------------------------------------------
__global__ void gather_kernel(float* __restrict__ out) {
    const int lane = threadIdx.x & 31;
    const int warp = threadIdx.x >> 5;
    const int n = blockIdx.y;
    const int b = blockIdx.x * 8 + warp;

    const float2 sf = __ldg(&g_SF[(size_t)b * NDIM + n]);   // uniform broadcast
    const float frac = sf.x;
    const int   lo   = __float_as_int(sf.y);

    const uint4* T0 = (const uint4*)(g_T16 + ((size_t)n * (KDIM + 1) + lo) * EDIM);
    const uint4* T1 = T0 + (EDIM / 8);
    float4* o = (float4*)(out + ((size_t)b * NDIM + n) * EDIM);

    // Front-batch all 4 independent loads (MLP=4)
    uint4 a0 = __ldg(&T0[lane]);
    uint4 c0 = __ldg(&T1[lane]);
    uint4 a1 = __ldg(&T0[lane + 32]);
    uint4 c1 = __ldg(&T1[lane + 32]);

#pragma unroll
    for (int j = 0; j < 2; j++) {
        const uint4& a  = j ? a1 : a0;
        const uint4& cc = j ? c1 : c0;
        const unsigned* ap = &a.x;
        const unsigned* cp = &cc.x;
        float4 r0, r1;
#pragma unroll
        for (int q = 0; q < 4; q++) {
            float2 av = __half22float2(*(const __half2*)&ap[q]);
            float2 cv = __half22float2(*(const __half2*)&cp[q]);
            float v0 = fmaxf(fmaf(frac, cv.x - av.x, av.x), 0.0f);
            float v1 = fmaxf(fmaf(frac, cv.y - av.y, av.y), 0.0f);
            if (q == 0)      { r0.x = v0; r0.y = v1; }
            else if (q == 1) { r0.z = v0; r0.w = v1; }
            else if (q == 2) { r1.x = v0; r1.y = v1; }
            else             { r1.z = v0; r1.w = v1; }
        }
        const int i = lane + 32 * j;
        __stcs(&o[2 * i],     r0);
        __stcs(&o[2 * i + 1], r1);
    }
}

extern "C" void kernel_launch(void* const* d_in, const int* in_sizes, int n_in,
                              void* d_out, int out_size) {
    const float* X      = (const float*)d_in[0];   // (B, N)
    const float* bnd    = (const float*)d_in[1];   // (N, K+1)
    const float* weight = (const float*)d_in[2];   // (N, K, E)
    const float* bias   = (const float*)d_in[3];   // (N, E)
    float* out = (float*)d_out;                    // (B, N, E)

    setup_kernel<<<PREFIX_BLOCKS + SEARCH_BLOCKS, 256>>>(X, bnd, weight, bias);

    dim3 grid(BDIM / 8, NDIM);
    gather_kernel<<<grid, 256>>>(out);
}

// round 4
// speedup vs baseline: 1.4469x; 1.4469x over previous
#include <cuda_runtime.h>
#include <cuda_fp16.h>
#include <cstdint>

// Problem dims (fixed): X:(B,N), boundaries:(N,K+1), weight:(N,K,E), bias:(N,E)
#define BDIM 4096
#define NDIM 64
#define KDIM 128
#define EDIM 512
#define EPS_F 1e-8f

// Prefix table T[n][k][e] (fp16): T[n][k][e] = bias[n][e] + sum_{j<k} w[n][j][e]
// out[b][n][e] = relu( lerp(T[n][bidx], T[n][bidx+1], frac) )
__device__ __half g_T16[(size_t)NDIM * (KDIM + 1) * EDIM];
// Per-(b,n) precomputed (frac, bidx), indexed b*N+n.
__device__ float2 g_SF[(size_t)BDIM * NDIM];

#define PREFIX_BLOCKS ((NDIM * 4 * EDIM) / 256)        // 512
#define SEARCH_BLOCKS ((BDIM * NDIM) / 256)            // 1024

// ---------------------------------------------------------------------------
// Setup (fused): blocks [0,512) build fp16 prefix table (4 k-chunks of 32 per
// (n,e)); blocks [512,1536) binary-search one (b,n) per thread into g_SF.
// ---------------------------------------------------------------------------
__global__ void setup_kernel(const float* __restrict__ X,
                             const float* __restrict__ bnd,
                             const float* __restrict__ weight,
                             const float* __restrict__ bias) {
    if (blockIdx.x < PREFIX_BLOCKS) {
        int t = blockIdx.x * blockDim.x + threadIdx.x;
        int e   = t % EDIM;
        int tmp = t / EDIM;          // n*4 + c
        int c   = tmp & 3;
        int n   = tmp >> 2;

        const float* wp = weight + (size_t)n * KDIM * EDIM + e;
        __half*      Tp = g_T16  + (size_t)n * (KDIM + 1) * EDIM + e;

        float acc = bias[n * EDIM + e];
        const int k0 = c * 32;

#pragma unroll 8
        for (int k = 0; k < k0; k++)
            acc += wp[(size_t)k * EDIM];

#pragma unroll
        for (int k = k0; k < k0 + 32; k++) {
            Tp[(size_t)k * EDIM] = __float2half_rn(acc);
            acc += wp[(size_t)k * EDIM];
        }
        if (c == 3)
            Tp[(size_t)KDIM * EDIM] = __float2half_rn(acc);
    } else {
        int i = (blockIdx.x - PREFIX_BLOCKS) * blockDim.x + threadIdx.x; // b*N+n
        int n = i & (NDIM - 1);
        const float x = X[i];
        const float* bn = bnd + (size_t)n * (KDIM + 1);

        int lo = 0, len = KDIM - 1;
        while (len > 0) {
            int half = len >> 1;
            bool pred = __ldg(&bn[1 + lo + half]) < x;
            lo  += pred ? (half + 1) : 0;
            len  = pred ? (len - half - 1) : half;
        }
        const float s  = __ldg(&bn[lo]);
        const float eb = __ldg(&bn[lo + 1]);
        const float frac = (x - s) / (eb - s + EPS_F);
        g_SF[i] = make_float2(frac, __int_as_float(lo));
    }
}

// ---------------------------------------------------------------------------
// Gather: one warp per (b,n). Loads precomputed (frac,lo), front-batches the
// 4 table LDG.128, lerps in fp32, writes the 2KB row into SMEM, then ONE
// cp.async.bulk (TMA bulk store) ships the row to GMEM — eliminating all
// per-lane STG wavefronts from the L1tex pipe.
// ---------------------------------------------------------------------------
__global__ void gather_kernel(float* __restrict__ out) {
    __shared__ float4 sm[8][EDIM / 4];                 // 8 rows x 2KB = 16KB

    const int lane = threadIdx.x & 31;
    const int warp = threadIdx.x >> 5;
    const int n = blockIdx.y;
    const int b = blockIdx.x * 8 + warp;

    const float2 sf = __ldg(&g_SF[(size_t)b * NDIM + n]);
    const float frac = sf.x;
    const int   lo   = __float_as_int(sf.y);

    const uint4* T0 = (const uint4*)(g_T16 + ((size_t)n * (KDIM + 1) + lo) * EDIM);
    const uint4* T1 = T0 + (EDIM / 8);

    uint4 a0 = __ldg(&T0[lane]);
    uint4 c0 = __ldg(&T1[lane]);
    uint4 a1 = __ldg(&T0[lane + 32]);
    uint4 c1 = __ldg(&T1[lane + 32]);

#pragma unroll
    for (int j = 0; j < 2; j++) {
        const uint4& a  = j ? a1 : a0;
        const uint4& cc = j ? c1 : c0;
        const unsigned* ap = &a.x;
        const unsigned* cp = &cc.x;
        float4 r0, r1;
#pragma unroll
        for (int q = 0; q < 4; q++) {
            float2 av = __half22float2(*(const __half2*)&ap[q]);
            float2 cv = __half22float2(*(const __half2*)&cp[q]);
            float v0 = fmaxf(fmaf(frac, cv.x - av.x, av.x), 0.0f);
            float v1 = fmaxf(fmaf(frac, cv.y - av.y, av.y), 0.0f);
            if (q == 0)      { r0.x = v0; r0.y = v1; }
            else if (q == 1) { r0.z = v0; r0.w = v1; }
            else if (q == 2) { r1.x = v0; r1.y = v1; }
            else             { r1.z = v0; r1.w = v1; }
        }
        const int i = lane + 32 * j;
        sm[warp][2 * i]     = r0;
        sm[warp][2 * i + 1] = r1;
    }

    __syncwarp();

    if (lane == 0) {
        // SMEM row -> GMEM row: one bulk async store per (b,n) row
        float* gdst = out + ((size_t)b * NDIM + n) * EDIM;
        uint32_t saddr;
        asm("{ .reg .u64 t; cvta.to.shared.u64 t, %1; cvt.u32.u64 %0, t; }"
            : "=r"(saddr) : "l"(&sm[warp][0]));
        asm volatile("fence.proxy.async.shared::cta;" ::: "memory");
        asm volatile(
            "cp.async.bulk.global.shared::cta.bulk_group [%0], [%1], %2;"
            :: "l"(gdst), "r"(saddr), "r"((int)(EDIM * 4)) : "memory");
        asm volatile("cp.async.bulk.commit_group;" ::: "memory");
        asm volatile("cp.async.bulk.wait_group 0;" ::: "memory");
    }
}

extern "C" void kernel_launch(void* const* d_in, const int* in_sizes, int n_in,
                              void* d_out, int out_size) {
    const float* X      = (const float*)d_in[0];   // (B, N)
    const float* bnd    = (const float*)d_in[1];   // (N, K+1)
    const float* weight = (const float*)d_in[2];   // (N, K, E)
    const float* bias   = (const float*)d_in[3];   // (N, E)
    float* out = (float*)d_out;                    // (B, N, E)

    setup_kernel<<<PREFIX_BLOCKS + SEARCH_BLOCKS, 256>>>(X, bnd, weight, bias);

    dim3 grid(BDIM / 8, NDIM);
    gather_kernel<<<grid, 256>>>(out);
}